// round 14
// baseline (speedup 1.0000x reference)
#include <cuda_runtime.h>
#include <cstdint>

// Problem constants
#define B_ 4
#define T_ 2048
#define C_ 1024
#define H_ 16
#define D_ 64
#define M_ (B_ * T_)

// Scratch: tf32-bit tensors (uint32) unless noted
__device__ uint32_t g_q[(size_t)B_ * H_ * T_ * D_];   // tf32 bits, q pre-scaled
__device__ uint32_t g_k[(size_t)B_ * H_ * T_ * D_];
__device__ uint32_t g_v[(size_t)B_ * H_ * T_ * D_];
__device__ uint32_t g_yt[(size_t)B_ * T_ * C_];       // attention out, tf32 bits
__device__ uint32_t g_xt[(size_t)M_ * C_];            // x, tf32 bits
__device__ uint32_t g_wt[4][(size_t)C_ * C_];         // W (k-major [k][n]), tf32 bits

// ---------------------------------------------------------------------------
// helpers
// ---------------------------------------------------------------------------
__device__ __forceinline__ uint32_t f2tf32(float f) {
    uint32_t u;
    asm("cvt.rna.tf32.f32 %0, %1;" : "=r"(u) : "f"(f));
    return u;
}
__device__ __forceinline__ float fexp2(float x) {
    float y;
    asm("ex2.approx.ftz.f32 %0, %1;" : "=f"(y) : "f"(x));
    return y;
}
__device__ __forceinline__ void mma_tf32_16x8x8(
    float* d, const uint32_t* a, const uint32_t* b, const float* c)
{
    asm volatile(
        "mma.sync.aligned.m16n8k8.row.col.f32.tf32.tf32.f32 "
        "{%0,%1,%2,%3}, {%4,%5,%6,%7}, {%8,%9}, {%10,%11,%12,%13};"
        : "=f"(d[0]), "=f"(d[1]), "=f"(d[2]), "=f"(d[3])
        : "r"(a[0]), "r"(a[1]), "r"(a[2]), "r"(a[3]),
          "r"(b[0]), "r"(b[1]),
          "f"(c[0]), "f"(c[1]), "f"(c[2]), "f"(c[3]));
}
__device__ __forceinline__ uint32_t smem_u32(const void* p) {
    uint32_t a;
    asm("{ .reg .u64 t; cvta.to.shared.u64 t, %1; cvt.u32.u64 %0, t; }"
        : "=r"(a) : "l"(p));
    return a;
}
__device__ __forceinline__ void cp_async16(uint32_t dst_smem, const void* src) {
    asm volatile("cp.async.cg.shared.global [%0], [%1], 16;"
                 :: "r"(dst_smem), "l"(src) : "memory");
}
#define CP_COMMIT()  asm volatile("cp.async.commit_group;" ::: "memory")
#define CP_WAIT(n)   asm volatile("cp.async.wait_group %0;" :: "n"(n) : "memory")

// ---------------------------------------------------------------------------
// fp32 -> tf32-bits conversions
// ---------------------------------------------------------------------------
__global__ __launch_bounds__(256)
void cvt_w_kernel(const float4* __restrict__ Wq, const float4* __restrict__ Wk,
                  const float4* __restrict__ Wv, const float4* __restrict__ Wp)
{
    const float4* src = (blockIdx.z == 0) ? Wq : (blockIdx.z == 1) ? Wk
                      : (blockIdx.z == 2) ? Wv : Wp;
    uint4* dst = (uint4*)g_wt[blockIdx.z];
    const int i = blockIdx.x * blockDim.x + threadIdx.x;
    float4 v = src[i];
    uint4 u;
    u.x = f2tf32(v.x); u.y = f2tf32(v.y);
    u.z = f2tf32(v.z); u.w = f2tf32(v.w);
    dst[i] = u;
}

__global__ __launch_bounds__(256)
void cvt_x_kernel(const float4* __restrict__ x)
{
    uint4* dst = (uint4*)g_xt;
    const int i = blockIdx.x * blockDim.x + threadIdx.x;
    float4 v = x[i];
    uint4 u;
    u.x = f2tf32(v.x); u.y = f2tf32(v.y);
    u.z = f2tf32(v.z); u.w = f2tf32(v.w);
    dst[i] = u;
}

// ---------------------------------------------------------------------------
// tf32 tensor-core GEMM (unchanged from R11/R12)
// ---------------------------------------------------------------------------
#define ASTR 36
#define BSTR 132
#define AS_WORDS (128 * ASTR)
#define BS_WORDS (32 * BSTR)
#define STG_WORDS (AS_WORDS + BS_WORDS)
#define GSMEM_BYTES (2 * STG_WORDS * 4)

__device__ __forceinline__ void gemm_stage(
    uint32_t sbase, int p, const uint32_t* __restrict__ At,
    const uint32_t* __restrict__ Bt, int m0, int n0, int k0, int tid)
{
    const uint32_t as = sbase + (uint32_t)p * STG_WORDS * 4;
    const uint32_t bs = as + AS_WORDS * 4;
    #pragma unroll
    for (int i = 0; i < 8; i++) {
        const int idx = tid + i * 128;
        const int row = idx >> 3;
        const int cg  = idx & 7;
        cp_async16(as + (uint32_t)(row * ASTR + cg * 4) * 4,
                   At + (size_t)(m0 + row) * C_ + k0 + cg * 4);
        const int k  = idx >> 5;
        const int n4 = (idx & 31) * 4;
        cp_async16(bs + (uint32_t)(k * BSTR + n4) * 4,
                   Bt + (size_t)(k0 + k) * C_ + n0 + n4);
    }
    CP_COMMIT();
}

__device__ __forceinline__ void gemm_body(
    const uint32_t* __restrict__ At, const uint32_t* __restrict__ Bt,
    const float* __restrict__ bias, void* __restrict__ out,
    int mode, float scale)
{
    extern __shared__ uint32_t smem[];
    const uint32_t sbase = smem_u32(smem);
    const int tid  = threadIdx.x;
    const int w    = tid >> 5;
    const int lane = tid & 31;
    const int g    = lane >> 2;
    const int tg   = lane & 3;
    const int m0   = blockIdx.y * 128;
    const int n0   = blockIdx.x * 128;
    const int wm   = (w & 1) * 64;
    const int wn   = (w >> 1) * 64;

    float acc[4][8][4];
    #pragma unroll
    for (int i = 0; i < 4; i++)
        #pragma unroll
        for (int j = 0; j < 8; j++)
            #pragma unroll
            for (int r = 0; r < 4; r++) acc[i][j][r] = 0.f;

    gemm_stage(sbase, 0, At, Bt, m0, n0, 0, tid);

    #define NCHUNK 32
    for (int c = 0; c < NCHUNK; c++) {
        const int p = c & 1;
        if (c + 1 < NCHUNK)
            gemm_stage(sbase, p ^ 1, At, Bt, m0, n0, (c + 1) * 32, tid);
        if (c + 1 < NCHUNK) CP_WAIT(1); else CP_WAIT(0);
        __syncthreads();

        const uint32_t* As = smem + (size_t)p * STG_WORDS;
        const uint32_t* Bs = As + AS_WORDS;
        #pragma unroll
        for (int ks = 0; ks < 4; ks++) {
            const int kk = ks * 8;
            uint32_t afr[4][4], bfr[8][2];
            #pragma unroll
            for (int mf = 0; mf < 4; mf++) {
                const int row = wm + mf * 16;
                afr[mf][0] = As[(row + g    ) * ASTR + kk + tg    ];
                afr[mf][1] = As[(row + g + 8) * ASTR + kk + tg    ];
                afr[mf][2] = As[(row + g    ) * ASTR + kk + tg + 4];
                afr[mf][3] = As[(row + g + 8) * ASTR + kk + tg + 4];
            }
            #pragma unroll
            for (int nf = 0; nf < 8; nf++) {
                const int col = wn + nf * 8 + g;
                bfr[nf][0] = Bs[(kk + tg    ) * BSTR + col];
                bfr[nf][1] = Bs[(kk + tg + 4) * BSTR + col];
            }
            #pragma unroll
            for (int mf = 0; mf < 4; mf++)
                #pragma unroll
                for (int nf = 0; nf < 8; nf++)
                    mma_tf32_16x8x8(acc[mf][nf], afr[mf], bfr[nf], acc[mf][nf]);
        }
        __syncthreads();
    }

    #pragma unroll
    for (int mf = 0; mf < 4; mf++) {
        #pragma unroll
        for (int nf = 0; nf < 8; nf++) {
            const int col = n0 + wn + nf * 8 + 2 * tg;
            const float b0 = bias[col], b1 = bias[col + 1];
            #pragma unroll
            for (int half = 0; half < 2; half++) {
                const int m = m0 + wm + mf * 16 + g + half * 8;
                const float v0 = acc[mf][nf][half * 2 + 0] + b0;
                const float v1 = acc[mf][nf][half * 2 + 1] + b1;
                if (mode == 0) {
                    float2* p2 = (float2*)((float*)out + (size_t)m * C_ + col);
                    *p2 = make_float2(v0, v1);
                } else {
                    const int bb = m >> 11;
                    const int t  = m & (T_ - 1);
                    const int h  = col >> 6;
                    const int d  = col & (D_ - 1);
                    uint32_t* p2 = (uint32_t*)out
                        + (((size_t)(bb * H_ + h) * T_ + t) * D_) + d;
                    p2[0] = f2tf32(v0 * scale);
                    p2[1] = f2tf32(v1 * scale);
                }
            }
        }
    }
}

#define QSCALE_ (0.125f * 1.4426950408889634f)

__global__ __launch_bounds__(128)
void qkv_gemm_kernel(const float* __restrict__ bq, const float* __restrict__ bk,
                     const float* __restrict__ bv)
{
    const float* bias; uint32_t* out; float scale;
    if (blockIdx.z == 0)      { bias = bq; out = g_q; scale = QSCALE_; }
    else if (blockIdx.z == 1) { bias = bk; out = g_k; scale = 1.f; }
    else                      { bias = bv; out = g_v; scale = 1.f; }
    gemm_body(g_xt, g_wt[blockIdx.z], bias, out, 1, scale);
}

__global__ __launch_bounds__(128)
void proj_gemm_kernel(const float* __restrict__ bp, float* __restrict__ out)
{
    gemm_body(g_yt, g_wt[3], bp, out, 0, 1.f);
}

// ---------------------------------------------------------------------------
// Flash attention: 256 threads / 8 warps, 16 rows per warp (mf=1).
// Double-buffered cp.async K/V pipeline + heavy-first ordering.
// Dynamic SMEM layout (words):
//   stage p (p=0,1): K at p*4352, V at p*4352+2176   (32 x 68 each)
//   Sp at 8704 + w*576                               (8 x 16 x 36)
// Total = (8704 + 4608) * 4 = 53248 bytes.
// ---------------------------------------------------------------------------
#define KVSTR_ 68
#define PSTR_  36
#define FL_KV_WORDS   (32 * KVSTR_)            // 2176
#define FL_STG_WORDS  (2 * FL_KV_WORDS)        // 4352
#define FL_SP_OFF     (2 * FL_STG_WORDS)       // 8704
#define FL_SMEM_BYTES ((FL_SP_OFF + 8 * 16 * PSTR_) * 4)   // 53248

__device__ __forceinline__ void flash_stage(
    uint32_t sbase, int p, const uint32_t* __restrict__ Kb,
    const uint32_t* __restrict__ Vb, int base, int tid)
{
    const uint32_t ks = sbase + (uint32_t)p * FL_STG_WORDS * 4;
    const uint32_t vs = ks + FL_KV_WORDS * 4;
    #pragma unroll
    for (int i = 0; i < 2; i++) {
        const int e   = tid + i * 256;         // 0..511
        const int key = e >> 4;
        const int c   = (e & 15) * 4;
        cp_async16(ks + (uint32_t)(key * KVSTR_ + c) * 4,
                   Kb + (size_t)(base + key) * D_ + c);
        cp_async16(vs + (uint32_t)(key * KVSTR_ + c) * 4,
                   Vb + (size_t)(base + key) * D_ + c);
    }
    CP_COMMIT();
}

__global__ __launch_bounds__(256)
void flash_tc_kernel()
{
    extern __shared__ uint32_t fsm[];
    const uint32_t sbase = smem_u32(fsm);

    const int bh   = blockIdx.y;
    const int qi   = (T_ / 128 - 1) - blockIdx.x;   // heavy blocks first
    const int tid  = threadIdx.x;                   // 0..255
    const int w    = tid >> 5;                      // 0..7
    const int lane = tid & 31;
    const int g    = lane >> 2;
    const int tg   = lane & 3;
    const int wrow = qi * 128 + w * 16;             // 16 rows per warp

    const uint32_t* Qb = g_q + (size_t)bh * T_ * D_;
    const uint32_t* Kb = g_k + (size_t)bh * T_ * D_;
    const uint32_t* Vb = g_v + (size_t)bh * T_ * D_;
    uint32_t (*Sp)[PSTR_] = (uint32_t (*)[PSTR_])(fsm + FL_SP_OFF + w * 16 * PSTR_);

    // Q fragments (16 rows): a0=(g,tg) a1=(g+8,tg) a2=(g,tg+4) a3=(g+8,tg+4)
    uint32_t qa[8][4];
    {
        const int r0 = wrow + g;
        const int r1 = r0 + 8;
        #pragma unroll
        for (int ks = 0; ks < 8; ks++) {
            qa[ks][0] = Qb[(size_t)r0 * D_ + ks * 8 + tg    ];
            qa[ks][1] = Qb[(size_t)r1 * D_ + ks * 8 + tg    ];
            qa[ks][2] = Qb[(size_t)r0 * D_ + ks * 8 + tg + 4];
            qa[ks][3] = Qb[(size_t)r1 * D_ + ks * 8 + tg + 4];
        }
    }

    float onf[8][4];
    #pragma unroll
    for (int nf = 0; nf < 8; nf++)
        #pragma unroll
        for (int c = 0; c < 4; c++) onf[nf][c] = 0.f;
    float mrow[2] = {-1e30f, -1e30f};
    float lrow[2] = {0.f, 0.f};

    const int ntile   = 4 * (qi + 1);
    const int maskBeg = 4 * qi;

    flash_stage(sbase, 0, Kb, Vb, 0, tid);

    for (int jt = 0; jt < ntile; jt++) {
        const int p = jt & 1;
        if (jt + 1 < ntile) {
            flash_stage(sbase, p ^ 1, Kb, Vb, (jt + 1) * 32, tid);
            CP_WAIT(1);
        } else {
            CP_WAIT(0);
        }
        __syncthreads();

        const uint32_t (*Kt)[KVSTR_] =
            (const uint32_t (*)[KVSTR_])(fsm + p * FL_STG_WORDS);
        const uint32_t (*Vt)[KVSTR_] =
            (const uint32_t (*)[KVSTR_])(fsm + p * FL_STG_WORDS + FL_KV_WORDS);
        const int base = jt * 32;

        // QK^T (16 x 32)
        float s[4][4];
        #pragma unroll
        for (int nf = 0; nf < 4; nf++)
            #pragma unroll
            for (int c = 0; c < 4; c++) s[nf][c] = 0.f;

        #pragma unroll
        for (int nf = 0; nf < 4; nf++) {
            #pragma unroll
            for (int ks = 0; ks < 8; ks++) {
                uint32_t b[2];
                b[0] = Kt[nf * 8 + g][ks * 8 + tg    ];
                b[1] = Kt[nf * 8 + g][ks * 8 + tg + 4];
                mma_tf32_16x8x8(s[nf], qa[ks], b, s[nf]);
            }
        }

        if (jt >= maskBeg) {
            #pragma unroll
            for (int nf = 0; nf < 4; nf++)
                #pragma unroll
                for (int c = 0; c < 4; c++) {
                    const int row = wrow + g + (c >> 1) * 8;
                    const int col = base + nf * 8 + 2 * tg + (c & 1);
                    if (col > row) s[nf][c] = -1e30f;
                }
        }

        // online softmax (base-2), 2 row-groups per warp
        #pragma unroll
        for (int h = 0; h < 2; h++) {
            float rmax = -1e30f;
            #pragma unroll
            for (int nf = 0; nf < 4; nf++)
                rmax = fmaxf(rmax, fmaxf(s[nf][h * 2], s[nf][h * 2 + 1]));
            rmax = fmaxf(rmax, __shfl_xor_sync(0xffffffffu, rmax, 1));
            rmax = fmaxf(rmax, __shfl_xor_sync(0xffffffffu, rmax, 2));

            const float mnew = fmaxf(mrow[h], rmax);
            const float corr = fexp2(mrow[h] - mnew);
            mrow[h] = mnew;

            float rsum = 0.f;
            #pragma unroll
            for (int nf = 0; nf < 4; nf++) {
                float p0 = fexp2(s[nf][h * 2    ] - mnew);
                float p1 = fexp2(s[nf][h * 2 + 1] - mnew);
                s[nf][h * 2    ] = p0;
                s[nf][h * 2 + 1] = p1;
                rsum += p0 + p1;
            }
            rsum += __shfl_xor_sync(0xffffffffu, rsum, 1);
            rsum += __shfl_xor_sync(0xffffffffu, rsum, 2);
            lrow[h] = lrow[h] * corr + rsum;

            #pragma unroll
            for (int nf = 0; nf < 8; nf++) {
                onf[nf][h * 2    ] *= corr;
                onf[nf][h * 2 + 1] *= corr;
            }
        }

        // stage P (tf32 bits) for A-operand layout (16 x 32 per warp)
        __syncwarp();
        #pragma unroll
        for (int nf = 0; nf < 4; nf++) {
            Sp[g    ][nf * 8 + 2 * tg    ] = f2tf32(s[nf][0]);
            Sp[g    ][nf * 8 + 2 * tg + 1] = f2tf32(s[nf][1]);
            Sp[g + 8][nf * 8 + 2 * tg    ] = f2tf32(s[nf][2]);
            Sp[g + 8][nf * 8 + 2 * tg + 1] = f2tf32(s[nf][3]);
        }
        __syncwarp();

        // P @ V  (16 x 32) @ (32 x 64)
        #pragma unroll
        for (int pk = 0; pk < 4; pk++) {
            uint32_t a[4];
            a[0] = Sp[g    ][pk * 8 + tg    ];
            a[1] = Sp[g + 8][pk * 8 + tg    ];
            a[2] = Sp[g    ][pk * 8 + tg + 4];
            a[3] = Sp[g + 8][pk * 8 + tg + 4];
            #pragma unroll
            for (int nf = 0; nf < 8; nf++) {
                uint32_t b[2];
                b[0] = Vt[pk * 8 + tg    ][nf * 8 + g];
                b[1] = Vt[pk * 8 + tg + 4][nf * 8 + g];
                mma_tf32_16x8x8(onf[nf], a, b, onf[nf]);
            }
        }
        __syncthreads();
    }

    // normalize, convert to tf32 bits, write to g_yt
    const int b  = bh >> 4;
    const int hh = bh & (H_ - 1);
    const float inv0 = 1.f / lrow[0];
    const float inv1 = 1.f / lrow[1];
    const int r0 = wrow + g;
    #pragma unroll
    for (int nf = 0; nf < 8; nf++) {
        const int d = nf * 8 + 2 * tg;
        uint32_t* p0 = &g_yt[((size_t)(b * T_ + r0) * C_) + hh * D_ + d];
        p0[0] = f2tf32(onf[nf][0] * inv0);
        p0[1] = f2tf32(onf[nf][1] * inv0);
        uint32_t* p1 = &g_yt[((size_t)(b * T_ + r0 + 8) * C_) + hh * D_ + d];
        p1[0] = f2tf32(onf[nf][2] * inv1);
        p1[1] = f2tf32(onf[nf][3] * inv1);
    }
}

// ---------------------------------------------------------------------------
extern "C" void kernel_launch(void* const* d_in, const int* in_sizes, int n_in,
                              void* d_out, int out_size)
{
    const float* x  = (const float*)d_in[0];
    const float* Wq = (const float*)d_in[1];
    const float* bq = (const float*)d_in[2];
    const float* Wk = (const float*)d_in[3];
    const float* bk = (const float*)d_in[4];
    const float* Wv = (const float*)d_in[5];
    const float* bv = (const float*)d_in[6];
    const float* Wp = (const float*)d_in[7];
    const float* bp = (const float*)d_in[8];
    float* out = (float*)d_out;

    cudaFuncSetAttribute(qkv_gemm_kernel,
                         cudaFuncAttributeMaxDynamicSharedMemorySize, GSMEM_BYTES);
    cudaFuncSetAttribute(proj_gemm_kernel,
                         cudaFuncAttributeMaxDynamicSharedMemorySize, GSMEM_BYTES);
    cudaFuncSetAttribute(flash_tc_kernel,
                         cudaFuncAttributeMaxDynamicSharedMemorySize, FL_SMEM_BYTES);

    const int wn4 = (C_ * C_) / 4;
    dim3 gw(wn4 / 256, 1, 4);
    cvt_w_kernel<<<gw, 256>>>((const float4*)Wq, (const float4*)Wk,
                              (const float4*)Wv, (const float4*)Wp);
    const int xn4 = (M_ * C_) / 4;
    cvt_x_kernel<<<xn4 / 256, 256>>>((const float4*)x);

    dim3 gq(C_ / 128, M_ / 128, 3);
    qkv_gemm_kernel<<<gq, 128, GSMEM_BYTES>>>(bq, bk, bv);

    dim3 gf(T_ / 128, B_ * H_);
    flash_tc_kernel<<<gf, 256, FL_SMEM_BYTES>>>();

    dim3 gp(C_ / 128, M_ / 128);
    proj_gemm_kernel<<<gp, 128, GSMEM_BYTES>>>(bp, out);
}